// round 11
// baseline (speedup 1.0000x reference)
#include <cuda_runtime.h>
#include <cuda_fp16.h>
#include <math.h>
#include <stdint.h>

// ---------------- problem constants ----------------
#define NE 8
#define HD 1024
#define FD 4096
#define NT 8192
#define MAXT 72                                  // max live m-tiles

// ---------------- GEMM tile config (fp16, m16n8k16), 2 CTAs/SM ----------------
#define BM 128
#define BN 128
#define BK 64                                    // 64 halves = 128B row
#define STAGES 3
#define A_STAGE_BYTES (BM * BK * 2)              // 16384
#define B_STAGE_BYTES (BN * BK * 2)              // 16384
#define STAGE_BYTES   (A_STAGE_BYTES + B_STAGE_BYTES)   // 32768
#define SMEM_BYTES    (STAGES * STAGE_BYTES)            // 98304 (x2 CTAs = 196608)

// ---------------- device scratch ----------------
__device__ __align__(16) __half g_w1h[(size_t)NE * FD * HD];
__device__ __align__(16) __half g_w2h[(size_t)NE * HD * FD];
__device__ __align__(16) __half g_xh[(size_t)NT * HD];
__device__ __align__(16) __half g_hbuf[(size_t)NT * FD];   // gelu(fc1), sorted order
__device__ int g_perm[NT];
__device__ int g_cnt[NE], g_cur[NE], g_off[NE + 1];
__device__ int g_tile_e[MAXT], g_tile_m[MAXT], g_ntiles;

// ---------------- helpers ----------------
__device__ __forceinline__ uint32_t smem_u32(const void* p) {
    uint32_t a;
    asm("{ .reg .u64 t; cvta.to.shared.u64 t, %1; cvt.u32.u64 %0, t; }" : "=r"(a) : "l"(p));
    return a;
}
__device__ __forceinline__ void cp16(uint32_t dst, const void* src) {
    asm volatile("cp.async.cg.shared.global [%0], [%1], 16;" :: "r"(dst), "l"(src));
}
__device__ __forceinline__ void cp_commit() {
    asm volatile("cp.async.commit_group;" ::: "memory");
}
template <int N>
__device__ __forceinline__ void cp_wait() {
    asm volatile("cp.async.wait_group %0;" :: "n"(N) : "memory");
}
__device__ __forceinline__ void ldsm_x4(uint32_t* r, uint32_t addr) {
    asm volatile("ldmatrix.sync.aligned.m8n8.x4.shared.b16 {%0,%1,%2,%3}, [%4];"
                 : "=r"(r[0]), "=r"(r[1]), "=r"(r[2]), "=r"(r[3]) : "r"(addr));
}
__device__ __forceinline__ void mma_f16(float* c, const uint32_t* a, uint32_t b0, uint32_t b1) {
    asm volatile(
        "mma.sync.aligned.m16n8k16.row.col.f32.f16.f16.f32 "
        "{%0,%1,%2,%3}, {%4,%5,%6,%7}, {%8,%9}, {%0,%1,%2,%3};"
        : "+f"(c[0]), "+f"(c[1]), "+f"(c[2]), "+f"(c[3])
        : "r"(a[0]), "r"(a[1]), "r"(a[2]), "r"(a[3]), "r"(b0), "r"(b1));
}
__device__ __forceinline__ float gelu_exact(float v) {
    return 0.5f * v * (1.0f + erff(v * 0.7071067811865476f));
}

// ---------------- routing: counting sort by expert + tile table ----------------
__global__ void k_zero() {
    int t = threadIdx.x;
    if (t < NE) { g_cnt[t] = 0; g_cur[t] = 0; }
}
__global__ void k_count(const int* __restrict__ ex) {
    int i = blockIdx.x * blockDim.x + threadIdx.x;
    if (i < NT) atomicAdd(&g_cnt[ex[i]], 1);
}
__global__ void k_scan() {
    int s = 0, nt = 0;
    for (int e = 0; e < NE; e++) {
        g_off[e] = s;
        for (int m0 = 0; m0 < g_cnt[e]; m0 += BM) {
            g_tile_e[nt] = e; g_tile_m[nt] = m0; nt++;
        }
        s += g_cnt[e];
    }
    g_off[NE] = s;
    g_ntiles = nt;
}
__global__ void k_scatter(const int* __restrict__ ex) {
    int i = blockIdx.x * blockDim.x + threadIdx.x;
    if (i < NT) {
        int e = ex[i];
        int r = atomicAdd(&g_cur[e], 1);
        g_perm[g_off[e] + r] = i;
    }
}

// ---------------- fp32 -> fp16 conversion ----------------
__global__ void k_cvt_h(const float4* __restrict__ src, uint4* __restrict__ dst, int n8) {
    int i = blockIdx.x * blockDim.x + threadIdx.x;
    int stride = gridDim.x * blockDim.x;
    for (; i < n8; i += stride) {
        float4 v0 = src[i * 2];
        float4 v1 = src[i * 2 + 1];
        __half2 h0 = __floats2half2_rn(v0.x, v0.y);
        __half2 h1 = __floats2half2_rn(v0.z, v0.w);
        __half2 h2 = __floats2half2_rn(v1.x, v1.y);
        __half2 h3 = __floats2half2_rn(v1.z, v1.w);
        uint4 o;
        o.x = *(uint32_t*)&h0; o.y = *(uint32_t*)&h1;
        o.z = *(uint32_t*)&h2; o.w = *(uint32_t*)&h3;
        dst[i] = o;
    }
}

// ---------------- fp16 mma.sync grouped GEMM (BM=BN=128, 2 CTAs/SM) ----------------
// blockIdx.y < g_ntiles: GEMM m-tile from the flat tile table.
// FC1 extra CTAs (blockIdx.y >= MAXT): grid-stride convert w2 fp32 -> g_w2h.

template <int KTOT, bool FC1>
__global__ __launch_bounds__(256, 2)
void k_gemm(const __half* __restrict__ Agm,
            const __half* __restrict__ Wh,
            const float*  __restrict__ gate,
            const int*    __restrict__ new_index,
            float*        __restrict__ outp,
            const float*  __restrict__ w2f)
{
    extern __shared__ __align__(128) char smem[];

    const int tid = threadIdx.x;

    if (FC1 && blockIdx.y >= MAXT) {
        // ---- w2 fp32 -> fp16 conversion slice (scheduled last) ----
        const int  cid    = (blockIdx.y - MAXT) * gridDim.x + blockIdx.x;
        const int  ncvt   = 16 * gridDim.x;
        const int  n8     = NE * HD * FD / 8;
        const int  stride = ncvt * 256;
        const float4* src = (const float4*)w2f;
        uint4*        dst = (uint4*)g_w2h;
        for (int i = cid * 256 + tid; i < n8; i += stride) {
            float4 v0 = src[i * 2];
            float4 v1 = src[i * 2 + 1];
            __half2 h0 = __floats2half2_rn(v0.x, v0.y);
            __half2 h1 = __floats2half2_rn(v0.z, v0.w);
            __half2 h2 = __floats2half2_rn(v1.x, v1.y);
            __half2 h3 = __floats2half2_rn(v1.z, v1.w);
            uint4 o;
            o.x = *(uint32_t*)&h0; o.y = *(uint32_t*)&h1;
            o.z = *(uint32_t*)&h2; o.w = *(uint32_t*)&h3;
            dst[i] = o;
        }
        return;
    }

    if ((int)blockIdx.y >= g_ntiles) return;
    const int e    = g_tile_e[blockIdx.y];
    const int m0   = g_tile_m[blockIdx.y];
    const int seg0 = g_off[e];
    const int mlen = g_off[e + 1] - seg0;
    const int n0   = blockIdx.x * BN;

    const int wid = tid >> 5;
    const int lid = tid & 31;
    const int wm  = wid & 3;       // m quarter (32 rows)
    const int wn  = wid >> 2;      // n half (64 cols)

    const uint32_t smem_b = smem_u32(smem);

    // ---- gmem load mapping: thread t -> row t>>1, 64B half (t&1) of the 128B row ----
    const int grow = tid >> 1;
    const int c4b  = (tid & 1) * 4;

    int arow_t = m0 + grow;
    if (arow_t >= mlen) arow_t = mlen - 1;          // clamp; masked in epilogue
    const int arow = FC1 ? g_perm[seg0 + arow_t] : (seg0 + arow_t);
    const __half* aSrc = Agm + (size_t)arow * KTOT + c4b * 8;

    const __half* wbase = Wh + (size_t)e * ((size_t)(FC1 ? FD : HD) * KTOT);
    const __half* bSrc  = wbase + (size_t)(n0 + grow) * KTOT + c4b * 8;

    uint32_t offA[4];
#pragma unroll
    for (int j = 0; j < 4; j++)
        offA[j] = (uint32_t)grow * 128u + (uint32_t)(((c4b + j) ^ (grow & 7)) << 4);

    // ---- ldmatrix per-lane address components ----
    const int lr  = lid & 7;
    const int lmi = lid >> 3;
    const int rowA0 = wm * 32 + ((lmi & 1) << 3) + lr;
    const int rowB0 = wn * 64 + ((lmi & 1) << 3) + lr;
    const int kHalf = lmi >> 1;
    const int s7A = rowA0 & 7;
    const int s7B = rowB0 & 7;

    float acc[2][8][4];
#pragma unroll
    for (int i = 0; i < 2; i++)
#pragma unroll
        for (int j = 0; j < 8; j++)
#pragma unroll
            for (int q = 0; q < 4; q++) acc[i][j][q] = 0.f;

    const int T = KTOT / BK;

    auto fill = [&](int s, int kt) {
        const uint32_t sa = smem_b + (uint32_t)s * STAGE_BYTES;
        const uint32_t sb = sa + A_STAGE_BYTES;
        const __half* a = aSrc + kt * BK;
        const __half* b = bSrc + kt * BK;
#pragma unroll
        for (int j = 0; j < 4; j++) cp16(sa + offA[j], a + j * 8);
#pragma unroll
        for (int j = 0; j < 4; j++) cp16(sb + offA[j], b + j * 8);
    };

#pragma unroll
    for (int s = 0; s < STAGES - 1; s++) { fill(s, s); cp_commit(); }

    for (int kt = 0; kt < T; kt++) {
        cp_wait<STAGES - 2>();
        __syncthreads();       // single barrier per iteration

        if (kt + STAGES - 1 < T) fill((kt + STAGES - 1) % STAGES, kt + STAGES - 1);
        cp_commit();

        const int s = kt % STAGES;
        const uint32_t aBase = smem_b + (uint32_t)s * STAGE_BYTES + (uint32_t)rowA0 * 128u;
        const uint32_t bBase = smem_b + (uint32_t)s * STAGE_BYTES + A_STAGE_BYTES +
                               (uint32_t)rowB0 * 128u;

#pragma unroll
        for (int kk = 0; kk < 4; kk++) {
            const uint32_t swA = (uint32_t)(((2 * kk + kHalf) ^ s7A) << 4);
            const uint32_t swB = (uint32_t)(((2 * kk + kHalf) ^ s7B) << 4);

            uint32_t af[2][4];
#pragma unroll
            for (int fm = 0; fm < 2; fm++)
                ldsm_x4(af[fm], aBase + (uint32_t)fm * 2048u + swA);

            uint32_t bf[4][4];
#pragma unroll
            for (int fn = 0; fn < 4; fn++)
                ldsm_x4(bf[fn], bBase + (uint32_t)fn * 2048u + swB);

#pragma unroll
            for (int fm = 0; fm < 2; fm++)
#pragma unroll
                for (int fn = 0; fn < 4; fn++) {
                    mma_f16(acc[fm][2 * fn + 0], af[fm], bf[fn][0], bf[fn][2]);
                    mma_f16(acc[fm][2 * fn + 1], af[fm], bf[fn][1], bf[fn][3]);
                }
        }
    }

    // ---- epilogue ----
    const int g = lid >> 2;
    const int q = lid & 3;

    if (FC1) {
#pragma unroll
        for (int fm = 0; fm < 2; fm++) {
#pragma unroll
            for (int h = 0; h < 2; h++) {
                const int row = m0 + wm * 32 + fm * 16 + h * 8 + g;
                if (row < mlen) {
                    __half* dst = g_hbuf + (size_t)(seg0 + row) * FD + n0 + wn * 64 + q * 2;
#pragma unroll
                    for (int fn = 0; fn < 8; fn++) {
                        __half2 v = __floats2half2_rn(gelu_exact(acc[fm][fn][h * 2 + 0]),
                                                      gelu_exact(acc[fm][fn][h * 2 + 1]));
                        *(__half2*)(dst + fn * 8) = v;
                    }
                }
            }
        }
    } else {
#pragma unroll
        for (int fm = 0; fm < 2; fm++) {
#pragma unroll
            for (int h = 0; h < 2; h++) {
                const int row = m0 + wm * 32 + fm * 16 + h * 8 + g;
                if (row < mlen) {
                    const int orig = g_perm[seg0 + row];
                    const float gg = gate[orig];
                    const int   dest = new_index[orig] >> 1;
                    float* orow = outp + (size_t)dest * HD + n0 + wn * 64 + q * 2;
#pragma unroll
                    for (int fn = 0; fn < 8; fn++) {
                        atomicAdd(orow + fn * 8 + 0, acc[fm][fn][h * 2 + 0] * gg);
                        atomicAdd(orow + fn * 8 + 1, acc[fm][fn][h * 2 + 1] * gg);
                    }
                }
            }
        }
    }
}

// ---------------- launch ----------------
extern "C" void kernel_launch(void* const* d_in, const int* in_sizes, int n_in,
                              void* d_out, int out_size) {
    const float* x         = (const float*)d_in[0];
    const float* gate      = (const float*)d_in[1];
    const int*   experts   = (const int*)  d_in[2];
    const int*   new_index = (const int*)  d_in[3];
    const float* w1        = (const float*)d_in[4];
    const float* w2        = (const float*)d_in[5];
    float*       out       = (float*)d_out;

    cudaFuncSetAttribute(k_gemm<HD, true>,  cudaFuncAttributeMaxDynamicSharedMemorySize, SMEM_BYTES);
    cudaFuncSetAttribute(k_gemm<FD, false>, cudaFuncAttributeMaxDynamicSharedMemorySize, SMEM_BYTES);

    cudaMemsetAsync(d_out, 0, (size_t)out_size * sizeof(float), 0);

    // routing + tile table
    k_zero<<<1, 32>>>();
    k_count<<<NT / 256, 256>>>(experts);
    k_scan<<<1, 1>>>();
    k_scatter<<<NT / 256, 256>>>(experts);

    // fp16 conversion of w1 and x (w2 converts inside the fc1 launch, overlapped)
    __half* w1h; __half* w2h; __half* xh; __half* hbuf;
    cudaGetSymbolAddress((void**)&w1h, g_w1h);
    cudaGetSymbolAddress((void**)&w2h, g_w2h);
    cudaGetSymbolAddress((void**)&xh,  g_xh);
    cudaGetSymbolAddress((void**)&hbuf, g_hbuf);
    k_cvt_h<<<4096, 256>>>((const float4*)w1, (uint4*)w1h, NE * FD * HD / 8);
    k_cvt_h<<<1024, 256>>>((const float4*)x,  (uint4*)xh,  NT * HD / 8);

    // fc1: gelu(x @ w1^T) -> g_hbuf; + trailing CTAs convert w2 -> g_w2h
    k_gemm<HD, true><<<dim3(FD / BN, MAXT + 16), 256, SMEM_BYTES>>>(
        xh, w1h, gate, new_index, out, w2);
    // fc2: (hbuf @ w2^T) * gate -> atomicAdd topk-scatter
    k_gemm<FD, false><<<dim3(HD / BN, MAXT), 256, SMEM_BYTES>>>(
        hbuf, w2h, gate, new_index, out, nullptr);
}

// round 12
// speedup vs baseline: 1.0406x; 1.0406x over previous
#include <cuda_runtime.h>
#include <cuda_fp16.h>
#include <math.h>
#include <stdint.h>

// ---------------- problem constants ----------------
#define NE 8
#define HD 1024
#define FD 4096
#define NT 8192
#define MAXT 72                                  // max live m-tiles

// ---------------- GEMM tile config (fp16, m16n8k16) ----------------
#define BM 128
#define BN 256
#define BK 64                                    // 64 halves = 128B row
#define STAGES 4
#define A_STAGE_BYTES (BM * BK * 2)              // 16384
#define B_STAGE_BYTES (BN * BK * 2)              // 32768
#define STAGE_BYTES   (A_STAGE_BYTES + B_STAGE_BYTES)   // 49152
#define SMEM_BYTES    (STAGES * STAGE_BYTES)            // 196608

// prep kernel block ranges
#define PREP_W1_BLKS 4096
#define PREP_X_BLKS  1024

// ---------------- device scratch ----------------
__device__ __align__(16) __half g_w1h[(size_t)NE * FD * HD];
__device__ __align__(16) __half g_w2h[(size_t)NE * HD * FD];
__device__ __align__(16) __half g_xh[(size_t)NT * HD];
__device__ __align__(16) __half g_hbuf[(size_t)NT * FD];   // gelu(fc1), sorted order
__device__ int g_perm[NT];
__device__ int g_off[NE + 1];
__device__ int g_tile_e[MAXT], g_tile_m[MAXT], g_ntiles;

// ---------------- helpers ----------------
__device__ __forceinline__ uint32_t smem_u32(const void* p) {
    uint32_t a;
    asm("{ .reg .u64 t; cvta.to.shared.u64 t, %1; cvt.u32.u64 %0, t; }" : "=r"(a) : "l"(p));
    return a;
}
__device__ __forceinline__ void cp16(uint32_t dst, const void* src) {
    asm volatile("cp.async.cg.shared.global [%0], [%1], 16;" :: "r"(dst), "l"(src));
}
__device__ __forceinline__ void cp_commit() {
    asm volatile("cp.async.commit_group;" ::: "memory");
}
template <int N>
__device__ __forceinline__ void cp_wait() {
    asm volatile("cp.async.wait_group %0;" :: "n"(N) : "memory");
}
__device__ __forceinline__ void ldsm_x4(uint32_t* r, uint32_t addr) {
    asm volatile("ldmatrix.sync.aligned.m8n8.x4.shared.b16 {%0,%1,%2,%3}, [%4];"
                 : "=r"(r[0]), "=r"(r[1]), "=r"(r[2]), "=r"(r[3]) : "r"(addr));
}
__device__ __forceinline__ void mma_f16(float* c, const uint32_t* a, uint32_t b0, uint32_t b1) {
    asm volatile(
        "mma.sync.aligned.m16n8k16.row.col.f32.f16.f16.f32 "
        "{%0,%1,%2,%3}, {%4,%5,%6,%7}, {%8,%9}, {%0,%1,%2,%3};"
        : "+f"(c[0]), "+f"(c[1]), "+f"(c[2]), "+f"(c[3])
        : "r"(a[0]), "r"(a[1]), "r"(a[2]), "r"(a[3]), "r"(b0), "r"(b1));
}
__device__ __forceinline__ float gelu_exact(float v) {
    return 0.5f * v * (1.0f + erff(v * 0.7071067811865476f));
}
__device__ __forceinline__ void cvt8(const float4* __restrict__ src, uint4* __restrict__ dst, int i) {
    float4 v0 = src[i * 2];
    float4 v1 = src[i * 2 + 1];
    __half2 h0 = __floats2half2_rn(v0.x, v0.y);
    __half2 h1 = __floats2half2_rn(v0.z, v0.w);
    __half2 h2 = __floats2half2_rn(v1.x, v1.y);
    __half2 h3 = __floats2half2_rn(v1.z, v1.w);
    uint4 o;
    o.x = *(uint32_t*)&h0; o.y = *(uint32_t*)&h1;
    o.z = *(uint32_t*)&h2; o.w = *(uint32_t*)&h3;
    dst[i] = o;
}

// ---------------- fused prep: routing (block 0) + w1 cvt + x cvt ----------------
__global__ void k_prep(const int* __restrict__ ex,
                       const float4* __restrict__ w1f,
                       const float4* __restrict__ xf)
{
    const int b   = blockIdx.x;
    const int tid = threadIdx.x;

    if (b == 0) {
        // ---- single-block routing: counting sort by expert + tile table ----
        __shared__ int s_cnt[NE], s_off[NE + 1], s_cur[NE];
        if (tid < NE) { s_cnt[tid] = 0; s_cur[tid] = 0; }
        __syncthreads();
        for (int i = tid; i < NT; i += blockDim.x)
            atomicAdd(&s_cnt[ex[i]], 1);
        __syncthreads();
        if (tid == 0) {
            int s = 0, nt = 0;
            for (int e = 0; e < NE; e++) {
                s_off[e] = s;
                g_off[e] = s;
                for (int m0 = 0; m0 < s_cnt[e]; m0 += BM) {
                    g_tile_e[nt] = e; g_tile_m[nt] = m0; nt++;
                }
                s += s_cnt[e];
            }
            s_off[NE] = s;
            g_off[NE] = s;
            g_ntiles  = nt;
        }
        __syncthreads();
        for (int i = tid; i < NT; i += blockDim.x) {
            int e = ex[i];
            int r = atomicAdd(&s_cur[e], 1);
            g_perm[s_off[e] + r] = i;
        }
        return;
    }

    if (b <= PREP_W1_BLKS) {
        // ---- w1 fp32 -> fp16 ----
        const int cid = b - 1;
        const int n8  = NE * FD * HD / 8;
        const int stride = PREP_W1_BLKS * 256;
        uint4* dst = (uint4*)g_w1h;
        for (int i = cid * 256 + tid; i < n8; i += stride)
            cvt8(w1f, dst, i);
        return;
    }

    // ---- x fp32 -> fp16 ----
    {
        const int cid = b - 1 - PREP_W1_BLKS;
        const int n8  = NT * HD / 8;
        const int stride = PREP_X_BLKS * 256;
        uint4* dst = (uint4*)g_xh;
        for (int i = cid * 256 + tid; i < n8; i += stride)
            cvt8(xf, dst, i);
    }
}

// ---------------- fp16 mma.sync grouped GEMM ----------------
// blockIdx.y < g_ntiles: GEMM m-tile from the flat tile table.
// FC1 extra CTAs (blockIdx.y >= MAXT): grid-stride convert w2 fp32 -> g_w2h,
// overlapped with fc1 compute (fc2 launches after fc1 completes).

template <int KTOT, bool FC1>
__global__ __launch_bounds__(256, 1)
void k_gemm(const __half* __restrict__ Agm,
            const __half* __restrict__ Wh,
            const float*  __restrict__ gate,
            const int*    __restrict__ new_index,
            float*        __restrict__ outp,
            const float*  __restrict__ w2f)
{
    extern __shared__ __align__(128) char smem[];

    const int tid = threadIdx.x;

    if (FC1 && blockIdx.y >= MAXT) {
        // ---- w2 fp32 -> fp16 conversion slice (256 CTAs, scheduled last) ----
        const int  cid    = (blockIdx.y - MAXT) * gridDim.x + blockIdx.x;   // 0..255
        const int  n8     = NE * HD * FD / 8;
        const int  stride = 256 * 256;
        const float4* src = (const float4*)w2f;
        uint4*        dst = (uint4*)g_w2h;
        for (int i = cid * 256 + tid; i < n8; i += stride)
            cvt8(src, dst, i);
        return;
    }

    if ((int)blockIdx.y >= g_ntiles) return;
    const int e    = g_tile_e[blockIdx.y];
    const int m0   = g_tile_m[blockIdx.y];
    const int seg0 = g_off[e];
    const int mlen = g_off[e + 1] - seg0;
    const int n0   = blockIdx.x * BN;

    const int wid = tid >> 5;
    const int lid = tid & 31;
    const int wm  = wid & 1;       // m half (64 rows)
    const int wn  = wid >> 1;      // n quarter (64 cols)

    const uint32_t smem_b = smem_u32(smem);

    // ---- gmem load mapping: thread t -> row t>>1, 64B half (t&1) of the 128B row ----
    const int grow = tid >> 1;
    const int c4b  = (tid & 1) * 4;

    int arow_t = m0 + grow;
    if (arow_t >= mlen) arow_t = mlen - 1;          // clamp; masked in epilogue
    const int arow = FC1 ? g_perm[seg0 + arow_t] : (seg0 + arow_t);
    const __half* aSrc = Agm + (size_t)arow * KTOT + c4b * 8;

    const __half* wbase = Wh + (size_t)e * ((size_t)(FC1 ? FD : HD) * KTOT);
    const __half* bSrc0 = wbase + (size_t)(n0 + grow)       * KTOT + c4b * 8;
    const __half* bSrc1 = wbase + (size_t)(n0 + grow + 128) * KTOT + c4b * 8;

    uint32_t offA[4], offB1[4];
#pragma unroll
    for (int j = 0; j < 4; j++) {
        offA[j]  = (uint32_t)grow * 128u + (uint32_t)(((c4b + j) ^ (grow & 7)) << 4);
        offB1[j] = (uint32_t)(grow + 128) * 128u +
                   (uint32_t)(((c4b + j) ^ ((grow + 128) & 7)) << 4);
    }

    // ---- ldmatrix per-lane address components ----
    const int lr  = lid & 7;
    const int lmi = lid >> 3;
    const int rowA0 = wm * 64 + ((lmi & 1) << 3) + lr;
    const int rowB0 = wn * 64 + ((lmi & 1) << 3) + lr;
    const int kHalf = lmi >> 1;
    const int s7A = rowA0 & 7;
    const int s7B = rowB0 & 7;

    float acc[4][8][4];
#pragma unroll
    for (int i = 0; i < 4; i++)
#pragma unroll
        for (int j = 0; j < 8; j++)
#pragma unroll
            for (int q = 0; q < 4; q++) acc[i][j][q] = 0.f;

    const int T = KTOT / BK;

    auto fill = [&](int s, int kt) {
        const uint32_t sa = smem_b + (uint32_t)s * STAGE_BYTES;
        const uint32_t sb = sa + A_STAGE_BYTES;
        const __half* a  = aSrc  + kt * BK;
        const __half* b0 = bSrc0 + kt * BK;
        const __half* b1 = bSrc1 + kt * BK;
#pragma unroll
        for (int j = 0; j < 4; j++) cp16(sa + offA[j],  a  + j * 8);
#pragma unroll
        for (int j = 0; j < 4; j++) cp16(sb + offA[j],  b0 + j * 8);
#pragma unroll
        for (int j = 0; j < 4; j++) cp16(sb + offB1[j], b1 + j * 8);
    };

#pragma unroll
    for (int s = 0; s < STAGES - 1; s++) { fill(s, s); cp_commit(); }

    for (int kt = 0; kt < T; kt++) {
        cp_wait<STAGES - 2>();
        __syncthreads();       // single barrier per iteration

        if (kt + STAGES - 1 < T) fill((kt + STAGES - 1) % STAGES, kt + STAGES - 1);
        cp_commit();

        const int s = kt % STAGES;
        const uint32_t aBase = smem_b + (uint32_t)s * STAGE_BYTES + (uint32_t)rowA0 * 128u;
        const uint32_t bBase = smem_b + (uint32_t)s * STAGE_BYTES + A_STAGE_BYTES +
                               (uint32_t)rowB0 * 128u;

#pragma unroll
        for (int kk = 0; kk < 4; kk++) {
            const uint32_t swA = (uint32_t)(((2 * kk + kHalf) ^ s7A) << 4);
            const uint32_t swB = (uint32_t)(((2 * kk + kHalf) ^ s7B) << 4);

            uint32_t af[4][4];
#pragma unroll
            for (int fm = 0; fm < 4; fm++)
                ldsm_x4(af[fm], aBase + (uint32_t)fm * 2048u + swA);

            uint32_t bf[4][4];
#pragma unroll
            for (int fn = 0; fn < 4; fn++)
                ldsm_x4(bf[fn], bBase + (uint32_t)fn * 2048u + swB);

#pragma unroll
            for (int fm = 0; fm < 4; fm++)
#pragma unroll
                for (int fn = 0; fn < 4; fn++) {
                    mma_f16(acc[fm][2 * fn + 0], af[fm], bf[fn][0], bf[fn][2]);
                    mma_f16(acc[fm][2 * fn + 1], af[fm], bf[fn][1], bf[fn][3]);
                }
        }
    }

    // ---- epilogue ----
    const int g = lid >> 2;
    const int q = lid & 3;

    if (FC1) {
#pragma unroll
        for (int fm = 0; fm < 4; fm++) {
#pragma unroll
            for (int h = 0; h < 2; h++) {
                const int row = m0 + wm * 64 + fm * 16 + h * 8 + g;
                if (row < mlen) {
                    __half* dst = g_hbuf + (size_t)(seg0 + row) * FD + n0 + wn * 64 + q * 2;
#pragma unroll
                    for (int fn = 0; fn < 8; fn++) {
                        __half2 v = __floats2half2_rn(gelu_exact(acc[fm][fn][h * 2 + 0]),
                                                      gelu_exact(acc[fm][fn][h * 2 + 1]));
                        *(__half2*)(dst + fn * 8) = v;
                    }
                }
            }
        }
    } else {
#pragma unroll
        for (int fm = 0; fm < 4; fm++) {
#pragma unroll
            for (int h = 0; h < 2; h++) {
                const int row = m0 + wm * 64 + fm * 16 + h * 8 + g;
                if (row < mlen) {
                    const int orig = g_perm[seg0 + row];
                    const float gg = gate[orig];
                    const int   dest = new_index[orig] >> 1;
                    float* orow = outp + (size_t)dest * HD + n0 + wn * 64 + q * 2;
#pragma unroll
                    for (int fn = 0; fn < 8; fn++) {
                        atomicAdd(orow + fn * 8 + 0, acc[fm][fn][h * 2 + 0] * gg);
                        atomicAdd(orow + fn * 8 + 1, acc[fm][fn][h * 2 + 1] * gg);
                    }
                }
            }
        }
    }
}

// ---------------- launch ----------------
extern "C" void kernel_launch(void* const* d_in, const int* in_sizes, int n_in,
                              void* d_out, int out_size) {
    const float* x         = (const float*)d_in[0];
    const float* gate      = (const float*)d_in[1];
    const int*   experts   = (const int*)  d_in[2];
    const int*   new_index = (const int*)  d_in[3];
    const float* w1        = (const float*)d_in[4];
    const float* w2        = (const float*)d_in[5];
    float*       out       = (float*)d_out;

    cudaFuncSetAttribute(k_gemm<HD, true>,  cudaFuncAttributeMaxDynamicSharedMemorySize, SMEM_BYTES);
    cudaFuncSetAttribute(k_gemm<FD, false>, cudaFuncAttributeMaxDynamicSharedMemorySize, SMEM_BYTES);

    cudaMemsetAsync(d_out, 0, (size_t)out_size * sizeof(float), 0);

    __half* w2h; __half* xh; __half* w1h; __half* hbuf;
    cudaGetSymbolAddress((void**)&w1h, g_w1h);
    cudaGetSymbolAddress((void**)&w2h, g_w2h);
    cudaGetSymbolAddress((void**)&xh,  g_xh);
    cudaGetSymbolAddress((void**)&hbuf, g_hbuf);

    // fused prep: block 0 routing; blocks 1..4096 w1 cvt; 4097..5120 x cvt
    k_prep<<<1 + PREP_W1_BLKS + PREP_X_BLKS, 256>>>(
        experts, (const float4*)w1, (const float4*)x);

    // fc1: gelu(x @ w1^T) -> g_hbuf; + 16 trailing y-blocks convert w2 -> g_w2h
    k_gemm<HD, true><<<dim3(FD / BN, MAXT + 16), 256, SMEM_BYTES>>>(
        xh, w1h, gate, new_index, out, w2);
    // fc2: (hbuf @ w2^T) * gate -> atomicAdd topk-scatter
    k_gemm<FD, false><<<dim3(HD / BN, MAXT), 256, SMEM_BYTES>>>(
        hbuf, w2h, gate, new_index, out, nullptr);
}